// round 14
// baseline (speedup 1.0000x reference)
#include <cuda_runtime.h>
#include <cuda_fp16.h>
#include <cstdint>

#define DD 64
#define MAXN 50000

// scratch (static __device__ — no allocations allowed)
__device__ float  g_in[MAXN * DD];    // x pre-filled, scatter adds -> In = x + agg
__device__ __half g_xh[MAXN * DD];    // fp16 copy of x (scatter read source)
__device__ __half g_P[MAXN * DD];     // fp16 node_emb @ W1a
__device__ __half g_Q[MAXN * DD];     // fp16 node_emb @ W1b + b1 (bias folded)
__device__ __half g_Weh[DD * DD];     // fp16 Wenc
__device__ __half g_W1h[2 * DD * DD]; // fp16 W1
__device__ int    g_shift;            // 0 = int32 edge_index, 1 = int64

struct alignas(16) h8 { __half2 a, b, c, d; };
struct alignas(8)  h4 { __half2 a, b; };

// ---------------------------------------------------------------------------
// Prep: g_in = x; g_xh = half(x); fp16 weight copies; dtype probe.
// (int64 with idx<50000 -> every odd 32-bit word == 0)
// ---------------------------------------------------------------------------
__global__ void k_prep(const float* __restrict__ x, const int* __restrict__ ei,
                       const float* __restrict__ Wenc, const float* __restrict__ W1,
                       int n4) {
    int i = blockIdx.x * blockDim.x + threadIdx.x;
    if (i < n4) {
        float4 v = ((const float4*)x)[i];
        ((float4*)g_in)[i] = v;
        h4 h;
        h.a = __floats2half2_rn(v.x, v.y);
        h.b = __floats2half2_rn(v.z, v.w);
        ((h4*)g_xh)[i] = h;
    }
    if (i < 4096) g_Weh[i] = __float2half(Wenc[i]);
    if (i < 8192) g_W1h[i] = __float2half(W1[i]);
    if (i == 0) {
        int z = 0;
#pragma unroll
        for (int k = 1; k < 32; k += 2) z |= ei[k];
        g_shift = (z == 0) ? 1 : 0;
    }
}

// ---------------------------------------------------------------------------
// Scatter: In[dst] += x[src]. 16 edges/warp.
// One coalesced 32-word index load per warp, shuffled out.
// 4 groups of 8 lanes; group g handles edges base+4r+g, r=0..3.
// Read: 8-lane LDG.128 of fp16 row (4 in flight); each lane's 8 halves feed
// two float4 atomics directly.
// ---------------------------------------------------------------------------
__global__ void k_scatter(const int* __restrict__ ei, int E) {
    int shift = g_shift;
    int t = blockIdx.x * blockDim.x + threadIdx.x;
    int warp = t >> 5;
    int lane = t & 31;
    long long base = (long long)warp * 16;

    int li = lane & 15;
    long long pos = (lane < 16) ? (base + li) : ((long long)E + base + li);
    int myidx = 0;
    if (base + li < E) myidx = ei[pos << shift];

    const unsigned FULL = 0xFFFFFFFFu;
    int g = lane >> 3;      // 0..3
    int j = lane & 7;       // 16B chunk of row (8 halves)

    int s[4], d[4];
    bool v[4];
#pragma unroll
    for (int r = 0; r < 4; r++) {
        s[r] = __shfl_sync(FULL, myidx, 4 * r + g);
        d[r] = __shfl_sync(FULL, myidx, 16 + 4 * r + g);
        v[r] = (base + 4 * r + g) < E;
    }

    float4 row[4];
#pragma unroll
    for (int r = 0; r < 4; r++) {
        row[r] = make_float4(0.f, 0.f, 0.f, 0.f);
        if (v[r]) row[r] = __ldcs((const float4*)(g_xh + (size_t)s[r] * 64) + j);
    }

#pragma unroll
    for (int r = 0; r < 4; r++) {
        if (!v[r]) continue;
        h8 hv = *(h8*)&row[r];
        float2 f0 = __half22float2(hv.a);
        float2 f1 = __half22float2(hv.b);
        float2 f2 = __half22float2(hv.c);
        float2 f3 = __half22float2(hv.d);
        float* dstrow = g_in + (size_t)d[r] * 64 + 8 * j;
        atomicAdd((float4*)dstrow,       make_float4(f0.x, f0.y, f1.x, f1.y));
        atomicAdd((float4*)(dstrow + 4), make_float4(f2.x, f2.y, f3.x, f3.y));
    }
}

// ---------------------------------------------------------------------------
// mma helpers
// ---------------------------------------------------------------------------
__device__ __forceinline__ unsigned smem_u32(const void* p) {
    return (unsigned)__cvta_generic_to_shared(p);
}
__device__ __forceinline__ void ldm_x4(unsigned addr, unsigned& a0, unsigned& a1,
                                       unsigned& a2, unsigned& a3) {
    asm volatile("ldmatrix.sync.aligned.m8n8.x4.shared.b16 {%0,%1,%2,%3}, [%4];"
                 : "=r"(a0), "=r"(a1), "=r"(a2), "=r"(a3) : "r"(addr));
}
__device__ __forceinline__ void ldm_x2t(unsigned addr, unsigned& b0, unsigned& b1) {
    asm volatile("ldmatrix.sync.aligned.m8n8.x2.trans.shared.b16 {%0,%1}, [%2];"
                 : "=r"(b0), "=r"(b1) : "r"(addr));
}
__device__ __forceinline__ void mma16816(float* c, unsigned a0, unsigned a1,
                                         unsigned a2, unsigned a3,
                                         unsigned b0, unsigned b1) {
    asm volatile(
        "mma.sync.aligned.m16n8k16.row.col.f32.f16.f16.f32 "
        "{%0,%1,%2,%3}, {%4,%5,%6,%7}, {%8,%9}, {%0,%1,%2,%3};"
        : "+f"(c[0]), "+f"(c[1]), "+f"(c[2]), "+f"(c[3])
        : "r"(a0), "r"(a1), "r"(a2), "r"(a3), "r"(b0), "r"(b1));
}

// ---------------------------------------------------------------------------
// Node kernel (tensor cores): block = 128 nodes, 8 warps.
// Warp w owns rows [16w, 16w+16).
//   phase1: emb = relu(In @ Wenc + be)   -> written back into sA (fp16)
//   phase2: [P|Q] = emb @ [W1a|W1b]      -> gmem fp16 (+b1 on Q)
// Weights staged from pre-converted fp16 globals (half2 copies).
// ---------------------------------------------------------------------------
#define NTILE_M 128
#define SA_ST 72
#define SW1_ST 136
#define NODE_SMEM_BYTES ((128 * 72 + 64 * 72 + 64 * SW1_ST) * 2 + 512)

__global__ void __launch_bounds__(256)
k_node(const float* __restrict__ benc, const float* __restrict__ b1, int N) {
    extern __shared__ __half smh[];
    __half* sA  = smh;                          // 128 x 72
    __half* sWe = smh + 128 * SA_ST;            // 64 x 72
    __half* sW1 = sWe + 64 * SA_ST;             // 64 x 136
    float*  sBe = (float*)(sW1 + 64 * SW1_ST);  // 64
    float*  sB1 = sBe + 64;                     // 64

    int tid = threadIdx.x;
    int node0 = blockIdx.x * NTILE_M;

    // stage Wenc (fp16 half2 copies)
    for (int i = tid; i < 2048; i += 256) {
        int k = i >> 5, c = i & 31;
        ((__half2*)(sWe + k * SA_ST))[c] = ((const __half2*)g_Weh)[i];
    }
    // stage W1: fp16 row (part*64+k) col-pair c -> sW1[k][part*64 + 2c]
    for (int i = tid; i < 4096; i += 256) {
        int row = i >> 5, c = i & 31;
        int part = row >> 6, k = row & 63;
        *(__half2*)(sW1 + k * SW1_ST + part * 64 + 2 * c) = ((const __half2*)g_W1h)[i];
    }
    if (tid < 64) { sBe[tid] = benc[tid]; sB1[tid] = b1[tid]; }

    // stage A = half(g_in)
    {
        const float4* in4 = (const float4*)g_in;
        for (int i = tid; i < 2048; i += 256) {
            int r = i >> 4, c = i & 15;
            int node = node0 + r;
            float4 v = make_float4(0.f, 0.f, 0.f, 0.f);
            if (node < N) v = in4[(size_t)node * 16 + c];
            __half2* dst = (__half2*)&sA[r * SA_ST + c * 4];
            dst[0] = __floats2half2_rn(v.x, v.y);
            dst[1] = __floats2half2_rn(v.z, v.w);
        }
    }
    __syncthreads();

    int wid  = tid >> 5;
    int lane = tid & 31;
    int arow = 16 * wid + (lane & 15);
    int acol_off = (lane >> 4) * 8;
    int r0 = 16 * wid + (lane >> 2);
    int cb = (lane & 3) * 2;

    unsigned sA_base  = smem_u32(sA);
    unsigned sWe_base = smem_u32(sWe);
    unsigned sW1_base = smem_u32(sW1);

    // ---- phase 1: C1[16x64] = A @ Wenc ----
    float c1[8][4];
#pragma unroll
    for (int n = 0; n < 8; n++)
#pragma unroll
        for (int i = 0; i < 4; i++) c1[n][i] = 0.f;

#pragma unroll
    for (int ks = 0; ks < 4; ks++) {
        int k = ks * 16;
        unsigned a0, a1, a2, a3;
        ldm_x4(sA_base + ((arow * SA_ST + k + acol_off) << 1), a0, a1, a2, a3);
#pragma unroll
        for (int nt = 0; nt < 8; nt++) {
            unsigned b0, b1v;
            ldm_x2t(sWe_base + (((k + (lane & 15)) * SA_ST + nt * 8) << 1), b0, b1v);
            mma16816(c1[nt], a0, a1, a2, a3, b0, b1v);
        }
    }

    // epilogue 1: relu(+bias) -> sA fp16
#pragma unroll
    for (int nt = 0; nt < 8; nt++) {
        int col = nt * 8 + cb;
        float be0 = sBe[col], be1 = sBe[col + 1];
        *(__half2*)&sA[r0 * SA_ST + col] =
            __floats2half2_rn(fmaxf(c1[nt][0] + be0, 0.f), fmaxf(c1[nt][1] + be1, 0.f));
        *(__half2*)&sA[(r0 + 8) * SA_ST + col] =
            __floats2half2_rn(fmaxf(c1[nt][2] + be0, 0.f), fmaxf(c1[nt][3] + be1, 0.f));
    }
    __syncwarp();

    // ---- phase 2: C2[16x128] = emb @ [W1a|W1b] ----
    float c2[16][4];
#pragma unroll
    for (int n = 0; n < 16; n++)
#pragma unroll
        for (int i = 0; i < 4; i++) c2[n][i] = 0.f;

#pragma unroll
    for (int ks = 0; ks < 4; ks++) {
        int k = ks * 16;
        unsigned a0, a1, a2, a3;
        ldm_x4(sA_base + ((arow * SA_ST + k + acol_off) << 1), a0, a1, a2, a3);
#pragma unroll
        for (int nt = 0; nt < 16; nt++) {
            unsigned b0, b1v;
            ldm_x2t(sW1_base + (((k + (lane & 15)) * SW1_ST + nt * 8) << 1), b0, b1v);
            mma16816(c2[nt], a0, a1, a2, a3, b0, b1v);
        }
    }

    // epilogue 2: nt<8 -> P, nt>=8 -> Q (+b1)
    int nodeA = node0 + r0;
    int nodeB = nodeA + 8;
    bool okA = nodeA < N, okB = nodeB < N;
#pragma unroll
    for (int nt = 0; nt < 8; nt++) {
        int col = nt * 8 + cb;
        if (okA) *(__half2*)&g_P[(size_t)nodeA * 64 + col] =
            __floats2half2_rn(c2[nt][0], c2[nt][1]);
        if (okB) *(__half2*)&g_P[(size_t)nodeB * 64 + col] =
            __floats2half2_rn(c2[nt][2], c2[nt][3]);
    }
#pragma unroll
    for (int nt = 8; nt < 16; nt++) {
        int col = (nt - 8) * 8 + cb;
        float b0f = sB1[col], b1f = sB1[col + 1];
        if (okA) *(__half2*)&g_Q[(size_t)nodeA * 64 + col] =
            __floats2half2_rn(c2[nt][0] + b0f, c2[nt][1] + b1f);
        if (okB) *(__half2*)&g_Q[(size_t)nodeB * 64 + col] =
            __floats2half2_rn(c2[nt][2] + b0f, c2[nt][3] + b1f);
    }
}

// ---------------------------------------------------------------------------
// Edge kernel: 16 edges/warp. One coalesced 32-word index load per warp,
// distributed by shuffle. 4 groups of 8 lanes; group g handles edges
// base+4r+g, r=0..3; 8 gathers in flight per thread.
//   out[e] = relu(P[src] + Q[dst]) . W2 + b2
// ---------------------------------------------------------------------------
__global__ void k_edge(const int* __restrict__ ei, const float* __restrict__ W2,
                       const float* __restrict__ b2, float* __restrict__ out, int E) {
    int shift = g_shift;
    int t = blockIdx.x * blockDim.x + threadIdx.x;
    int warp = t >> 5;
    int lane = t & 31;
    long long base = (long long)warp * 16;

    int li = lane & 15;
    long long pos = (lane < 16) ? (base + li) : ((long long)E + base + li);
    int myidx = 0;
    if (base + li < E) myidx = ei[pos << shift];

    const unsigned FULL = 0xFFFFFFFFu;
    int g   = lane >> 3;   // 0..3
    int cid = lane & 7;    // 16B chunk within row

    int s[4], d[4];
#pragma unroll
    for (int r = 0; r < 4; r++) {
        s[r] = __shfl_sync(FULL, myidx, 4 * r + g);
        d[r] = __shfl_sync(FULL, myidx, 16 + 4 * r + g);
    }

    const float4* Pf = (const float4*)g_P;
    const float4* Qf = (const float4*)g_Q;
    float4 pr[4], qr[4];
#pragma unroll
    for (int r = 0; r < 4; r++) {
        pr[r] = __ldcs(Pf + (size_t)s[r] * 8 + cid);
        qr[r] = __ldcs(Qf + (size_t)d[r] * 8 + cid);
    }

    float4 w0 = __ldg((const float4*)W2 + 2 * cid);
    float4 w1 = __ldg((const float4*)W2 + 2 * cid + 1);
    float bias = __ldg(b2);
    const __half2 hz = __float2half2_rn(0.f);

#pragma unroll
    for (int r = 0; r < 4; r++) {
        h8 p = *(h8*)&pr[r];
        h8 q = *(h8*)&qr[r];
        float2 h0 = __half22float2(__hmax2(__hadd2(p.a, q.a), hz));
        float2 h1 = __half22float2(__hmax2(__hadd2(p.b, q.b), hz));
        float2 h2 = __half22float2(__hmax2(__hadd2(p.c, q.c), hz));
        float2 h3 = __half22float2(__hmax2(__hadd2(p.d, q.d), hz));
        float sacc = h0.x * w0.x + h0.y * w0.y + h1.x * w0.z + h1.y * w0.w
                   + h2.x * w1.x + h2.y * w1.y + h3.x * w1.z + h3.y * w1.w;
        sacc += __shfl_xor_sync(FULL, sacc, 4);
        sacc += __shfl_xor_sync(FULL, sacc, 2);
        sacc += __shfl_xor_sync(FULL, sacc, 1);
        long long e = base + 4 * r + g;
        if (cid == 0 && e < E) out[e] = sacc + bias;
    }
}

// ---------------------------------------------------------------------------
extern "C" void kernel_launch(void* const* d_in, const int* in_sizes, int n_in,
                              void* d_out, int out_size) {
    const float* x    = (const float*)d_in[0];
    const int*   ei   = (const int*)d_in[1];
    const float* Wenc = (const float*)d_in[2];
    const float* benc = (const float*)d_in[3];
    const float* W1   = (const float*)d_in[4];
    const float* b1   = (const float*)d_in[5];
    const float* W2   = (const float*)d_in[6];
    const float* b2   = (const float*)d_in[7];
    float* out = (float*)d_out;

    int N = in_sizes[0] / DD;          // 50000
    int E = in_sizes[1] / 2;           // 800000

    int n4 = N * DD / 4;
    k_prep<<<(n4 + 255) / 256, 256>>>(x, ei, Wenc, W1, n4);

    {
        long long warps = ((long long)E + 15) / 16;
        long long threads = warps * 32;
        int blocks = (int)((threads + 255) / 256);
        k_scatter<<<blocks, 256>>>(ei, E);
    }

    {
        int blocks = (N + NTILE_M - 1) / NTILE_M;
        k_node<<<blocks, 256, NODE_SMEM_BYTES>>>(benc, b1, N);
    }

    {
        long long warps = ((long long)E + 15) / 16;
        long long threads = warps * 32;
        int blocks = (int)((threads + 255) / 256);
        k_edge<<<blocks, 256>>>(ei, W2, b2, out, E);
    }
}

// round 16
// speedup vs baseline: 1.2381x; 1.2381x over previous
#include <cuda_runtime.h>
#include <cuda_fp16.h>
#include <cstdint>

#define DD 64
#define MAXN 50000

// scratch (static __device__ — no allocations allowed)
__device__ float  g_in[MAXN * DD];    // x pre-filled, scatter adds -> In = x + agg
__device__ __half g_xh[MAXN * DD];    // fp16 copy of x (scatter read source)
__device__ __half g_P[MAXN * DD];     // fp16 node_emb @ W1a
__device__ __half g_Q[MAXN * DD];     // fp16 node_emb @ W1b + b1 (bias folded)
__device__ __half g_Weh[DD * DD];     // fp16 Wenc
__device__ __half g_W1h[2 * DD * DD]; // fp16 W1
__device__ int    g_shift;            // 0 = int32 edge_index, 1 = int64

struct alignas(16) h8 { __half2 a, b, c, d; };
struct alignas(8)  h4 { __half2 a, b; };

// ---------------------------------------------------------------------------
// Prep: g_in = x; g_xh = half(x); fp16 weight copies; dtype probe.
// (int64 with idx<50000 -> every odd 32-bit word == 0)
// ---------------------------------------------------------------------------
__global__ void k_prep(const float* __restrict__ x, const int* __restrict__ ei,
                       const float* __restrict__ Wenc, const float* __restrict__ W1,
                       int n4) {
    int i = blockIdx.x * blockDim.x + threadIdx.x;
    if (i < n4) {
        float4 v = ((const float4*)x)[i];
        ((float4*)g_in)[i] = v;
        h4 h;
        h.a = __floats2half2_rn(v.x, v.y);
        h.b = __floats2half2_rn(v.z, v.w);
        ((h4*)g_xh)[i] = h;
    }
    if (i < 4096) g_Weh[i] = __float2half(Wenc[i]);
    if (i < 8192) g_W1h[i] = __float2half(W1[i]);
    if (i == 0) {
        int z = 0;
#pragma unroll
        for (int k = 1; k < 32; k += 2) z |= ei[k];
        g_shift = (z == 0) ? 1 : 0;
    }
}

// ---------------------------------------------------------------------------
// Scatter (round-9 config, measured good): In[dst] += x[src].
// 4 edges/warp, cooperative index load (8 words) + shuffle.
// 2 serial edges per half-warp; 16 lanes/edge; float2 fp16 row reads;
// one float4 atomic per lane. High thread count hides atomic latency.
// ---------------------------------------------------------------------------
__global__ void k_scatter(const int* __restrict__ ei, int E) {
    int shift = g_shift;
    int t = blockIdx.x * blockDim.x + threadIdx.x;
    int warp = t >> 5;
    int lane = t & 31;
    long long base = (long long)warp * 4;

    int l  = lane & 7;
    int li = l & 3;
    long long pos = (l < 4) ? (base + li) : ((long long)E + base + li);
    int myidx = 0;
    if (base + li < E) myidx = ei[pos << shift];

    const unsigned FULL = 0xFFFFFFFFu;
    int half = lane >> 4;
    int sub  = lane & 15;
    int sA = __shfl_sync(FULL, myidx, half);
    int sB = __shfl_sync(FULL, myidx, 2 + half);
    int dA = __shfl_sync(FULL, myidx, 4 + half);
    int dB = __shfl_sync(FULL, myidx, 6 + half);
    bool vA = (base + half) < E;
    bool vB = (base + 2 + half) < E;

    float2 rA = make_float2(0.f, 0.f), rB = make_float2(0.f, 0.f);
    if (vA) rA = __ldcs((const float2*)(g_xh + (size_t)sA * 64) + sub);
    if (vB) rB = __ldcs((const float2*)(g_xh + (size_t)sB * 64) + sub);

    if (vA) {
        h4 hv = *(h4*)&rA;
        float2 f0 = __half22float2(hv.a);
        float2 f1 = __half22float2(hv.b);
        atomicAdd((float4*)(g_in + (size_t)dA * 64) + sub,
                  make_float4(f0.x, f0.y, f1.x, f1.y));
    }
    if (vB) {
        h4 hv = *(h4*)&rB;
        float2 f0 = __half22float2(hv.a);
        float2 f1 = __half22float2(hv.b);
        atomicAdd((float4*)(g_in + (size_t)dB * 64) + sub,
                  make_float4(f0.x, f0.y, f1.x, f1.y));
    }
}

// ---------------------------------------------------------------------------
// mma helpers
// ---------------------------------------------------------------------------
__device__ __forceinline__ unsigned smem_u32(const void* p) {
    return (unsigned)__cvta_generic_to_shared(p);
}
__device__ __forceinline__ void ldm_x4(unsigned addr, unsigned& a0, unsigned& a1,
                                       unsigned& a2, unsigned& a3) {
    asm volatile("ldmatrix.sync.aligned.m8n8.x4.shared.b16 {%0,%1,%2,%3}, [%4];"
                 : "=r"(a0), "=r"(a1), "=r"(a2), "=r"(a3) : "r"(addr));
}
__device__ __forceinline__ void ldm_x2t(unsigned addr, unsigned& b0, unsigned& b1) {
    asm volatile("ldmatrix.sync.aligned.m8n8.x2.trans.shared.b16 {%0,%1}, [%2];"
                 : "=r"(b0), "=r"(b1) : "r"(addr));
}
__device__ __forceinline__ void mma16816(float* c, unsigned a0, unsigned a1,
                                         unsigned a2, unsigned a3,
                                         unsigned b0, unsigned b1) {
    asm volatile(
        "mma.sync.aligned.m16n8k16.row.col.f32.f16.f16.f32 "
        "{%0,%1,%2,%3}, {%4,%5,%6,%7}, {%8,%9}, {%0,%1,%2,%3};"
        : "+f"(c[0]), "+f"(c[1]), "+f"(c[2]), "+f"(c[3])
        : "r"(a0), "r"(a1), "r"(a2), "r"(a3), "r"(b0), "r"(b1));
}

// ---------------------------------------------------------------------------
// Node kernel (tensor cores): block = 128 nodes, 8 warps.
// Warp w owns rows [16w, 16w+16).
//   phase1: emb = relu(In @ Wenc + be)   -> written back into sA (fp16)
//   phase2: [P|Q] = emb @ [W1a|W1b]      -> gmem fp16 (+b1 on Q)
// Weights staged from pre-converted fp16 globals (half2 copies).
// ---------------------------------------------------------------------------
#define NTILE_M 128
#define SA_ST 72
#define SW1_ST 136
#define NODE_SMEM_BYTES ((128 * 72 + 64 * 72 + 64 * SW1_ST) * 2 + 512)

__global__ void __launch_bounds__(256)
k_node(const float* __restrict__ benc, const float* __restrict__ b1, int N) {
    extern __shared__ __half smh[];
    __half* sA  = smh;                          // 128 x 72
    __half* sWe = smh + 128 * SA_ST;            // 64 x 72
    __half* sW1 = sWe + 64 * SA_ST;             // 64 x 136
    float*  sBe = (float*)(sW1 + 64 * SW1_ST);  // 64
    float*  sB1 = sBe + 64;                     // 64

    int tid = threadIdx.x;
    int node0 = blockIdx.x * NTILE_M;

    // stage Wenc (fp16 half2 copies)
    for (int i = tid; i < 2048; i += 256) {
        int k = i >> 5, c = i & 31;
        ((__half2*)(sWe + k * SA_ST))[c] = ((const __half2*)g_Weh)[i];
    }
    // stage W1: fp16 row (part*64+k) col-pair c -> sW1[k][part*64 + 2c]
    for (int i = tid; i < 4096; i += 256) {
        int row = i >> 5, c = i & 31;
        int part = row >> 6, k = row & 63;
        *(__half2*)(sW1 + k * SW1_ST + part * 64 + 2 * c) = ((const __half2*)g_W1h)[i];
    }
    if (tid < 64) { sBe[tid] = benc[tid]; sB1[tid] = b1[tid]; }

    // stage A = half(g_in)
    {
        const float4* in4 = (const float4*)g_in;
        for (int i = tid; i < 2048; i += 256) {
            int r = i >> 4, c = i & 15;
            int node = node0 + r;
            float4 v = make_float4(0.f, 0.f, 0.f, 0.f);
            if (node < N) v = in4[(size_t)node * 16 + c];
            __half2* dst = (__half2*)&sA[r * SA_ST + c * 4];
            dst[0] = __floats2half2_rn(v.x, v.y);
            dst[1] = __floats2half2_rn(v.z, v.w);
        }
    }
    __syncthreads();

    int wid  = tid >> 5;
    int lane = tid & 31;
    int arow = 16 * wid + (lane & 15);
    int acol_off = (lane >> 4) * 8;
    int r0 = 16 * wid + (lane >> 2);
    int cb = (lane & 3) * 2;

    unsigned sA_base  = smem_u32(sA);
    unsigned sWe_base = smem_u32(sWe);
    unsigned sW1_base = smem_u32(sW1);

    // ---- phase 1: C1[16x64] = A @ Wenc ----
    float c1[8][4];
#pragma unroll
    for (int n = 0; n < 8; n++)
#pragma unroll
        for (int i = 0; i < 4; i++) c1[n][i] = 0.f;

#pragma unroll
    for (int ks = 0; ks < 4; ks++) {
        int k = ks * 16;
        unsigned a0, a1, a2, a3;
        ldm_x4(sA_base + ((arow * SA_ST + k + acol_off) << 1), a0, a1, a2, a3);
#pragma unroll
        for (int nt = 0; nt < 8; nt++) {
            unsigned b0, b1v;
            ldm_x2t(sWe_base + (((k + (lane & 15)) * SA_ST + nt * 8) << 1), b0, b1v);
            mma16816(c1[nt], a0, a1, a2, a3, b0, b1v);
        }
    }

    // epilogue 1: relu(+bias) -> sA fp16
#pragma unroll
    for (int nt = 0; nt < 8; nt++) {
        int col = nt * 8 + cb;
        float be0 = sBe[col], be1 = sBe[col + 1];
        *(__half2*)&sA[r0 * SA_ST + col] =
            __floats2half2_rn(fmaxf(c1[nt][0] + be0, 0.f), fmaxf(c1[nt][1] + be1, 0.f));
        *(__half2*)&sA[(r0 + 8) * SA_ST + col] =
            __floats2half2_rn(fmaxf(c1[nt][2] + be0, 0.f), fmaxf(c1[nt][3] + be1, 0.f));
    }
    __syncwarp();

    // ---- phase 2: C2[16x128] = emb @ [W1a|W1b] ----
    float c2[16][4];
#pragma unroll
    for (int n = 0; n < 16; n++)
#pragma unroll
        for (int i = 0; i < 4; i++) c2[n][i] = 0.f;

#pragma unroll
    for (int ks = 0; ks < 4; ks++) {
        int k = ks * 16;
        unsigned a0, a1, a2, a3;
        ldm_x4(sA_base + ((arow * SA_ST + k + acol_off) << 1), a0, a1, a2, a3);
#pragma unroll
        for (int nt = 0; nt < 16; nt++) {
            unsigned b0, b1v;
            ldm_x2t(sW1_base + (((k + (lane & 15)) * SW1_ST + nt * 8) << 1), b0, b1v);
            mma16816(c2[nt], a0, a1, a2, a3, b0, b1v);
        }
    }

    // epilogue 2: nt<8 -> P, nt>=8 -> Q (+b1)
    int nodeA = node0 + r0;
    int nodeB = nodeA + 8;
    bool okA = nodeA < N, okB = nodeB < N;
#pragma unroll
    for (int nt = 0; nt < 8; nt++) {
        int col = nt * 8 + cb;
        if (okA) *(__half2*)&g_P[(size_t)nodeA * 64 + col] =
            __floats2half2_rn(c2[nt][0], c2[nt][1]);
        if (okB) *(__half2*)&g_P[(size_t)nodeB * 64 + col] =
            __floats2half2_rn(c2[nt][2], c2[nt][3]);
    }
#pragma unroll
    for (int nt = 8; nt < 16; nt++) {
        int col = (nt - 8) * 8 + cb;
        float b0f = sB1[col], b1f = sB1[col + 1];
        if (okA) *(__half2*)&g_Q[(size_t)nodeA * 64 + col] =
            __floats2half2_rn(c2[nt][0] + b0f, c2[nt][1] + b1f);
        if (okB) *(__half2*)&g_Q[(size_t)nodeB * 64 + col] =
            __floats2half2_rn(c2[nt][2] + b0f, c2[nt][3] + b1f);
    }
}

// ---------------------------------------------------------------------------
// Edge kernel: 16 edges/warp. One coalesced 32-word index load per warp,
// distributed by shuffle. 4 groups of 8 lanes; group g handles edges
// base+4r+g, r=0..3; 8 gathers in flight per thread.
//   out[e] = relu(P[src] + Q[dst]) . W2 + b2
// ---------------------------------------------------------------------------
__global__ void k_edge(const int* __restrict__ ei, const float* __restrict__ W2,
                       const float* __restrict__ b2, float* __restrict__ out, int E) {
    int shift = g_shift;
    int t = blockIdx.x * blockDim.x + threadIdx.x;
    int warp = t >> 5;
    int lane = t & 31;
    long long base = (long long)warp * 16;

    int li = lane & 15;
    long long pos = (lane < 16) ? (base + li) : ((long long)E + base + li);
    int myidx = 0;
    if (base + li < E) myidx = ei[pos << shift];

    const unsigned FULL = 0xFFFFFFFFu;
    int g   = lane >> 3;   // 0..3
    int cid = lane & 7;    // 16B chunk within row

    int s[4], d[4];
#pragma unroll
    for (int r = 0; r < 4; r++) {
        s[r] = __shfl_sync(FULL, myidx, 4 * r + g);
        d[r] = __shfl_sync(FULL, myidx, 16 + 4 * r + g);
    }

    const float4* Pf = (const float4*)g_P;
    const float4* Qf = (const float4*)g_Q;
    float4 pr[4], qr[4];
#pragma unroll
    for (int r = 0; r < 4; r++) {
        pr[r] = __ldcs(Pf + (size_t)s[r] * 8 + cid);
        qr[r] = __ldcs(Qf + (size_t)d[r] * 8 + cid);
    }

    float4 w0 = __ldg((const float4*)W2 + 2 * cid);
    float4 w1 = __ldg((const float4*)W2 + 2 * cid + 1);
    float bias = __ldg(b2);
    const __half2 hz = __float2half2_rn(0.f);

#pragma unroll
    for (int r = 0; r < 4; r++) {
        h8 p = *(h8*)&pr[r];
        h8 q = *(h8*)&qr[r];
        float2 h0 = __half22float2(__hmax2(__hadd2(p.a, q.a), hz));
        float2 h1 = __half22float2(__hmax2(__hadd2(p.b, q.b), hz));
        float2 h2 = __half22float2(__hmax2(__hadd2(p.c, q.c), hz));
        float2 h3 = __half22float2(__hmax2(__hadd2(p.d, q.d), hz));
        float sacc = h0.x * w0.x + h0.y * w0.y + h1.x * w0.z + h1.y * w0.w
                   + h2.x * w1.x + h2.y * w1.y + h3.x * w1.z + h3.y * w1.w;
        sacc += __shfl_xor_sync(FULL, sacc, 4);
        sacc += __shfl_xor_sync(FULL, sacc, 2);
        sacc += __shfl_xor_sync(FULL, sacc, 1);
        long long e = base + 4 * r + g;
        if (cid == 0 && e < E) out[e] = sacc + bias;
    }
}

// ---------------------------------------------------------------------------
extern "C" void kernel_launch(void* const* d_in, const int* in_sizes, int n_in,
                              void* d_out, int out_size) {
    const float* x    = (const float*)d_in[0];
    const int*   ei   = (const int*)d_in[1];
    const float* Wenc = (const float*)d_in[2];
    const float* benc = (const float*)d_in[3];
    const float* W1   = (const float*)d_in[4];
    const float* b1   = (const float*)d_in[5];
    const float* W2   = (const float*)d_in[6];
    const float* b2   = (const float*)d_in[7];
    float* out = (float*)d_out;

    int N = in_sizes[0] / DD;          // 50000
    int E = in_sizes[1] / 2;           // 800000

    int n4 = N * DD / 4;
    k_prep<<<(n4 + 255) / 256, 256>>>(x, ei, Wenc, W1, n4);

    {
        long long warps = ((long long)E + 3) / 4;
        long long threads = warps * 32;
        int blocks = (int)((threads + 255) / 256);
        k_scatter<<<blocks, 256>>>(ei, E);
    }

    {
        int blocks = (N + NTILE_M - 1) / NTILE_M;
        k_node<<<blocks, 256, NODE_SMEM_BYTES>>>(benc, b1, N);
    }

    {
        long long warps = ((long long)E + 15) / 16;
        long long threads = warps * 32;
        int blocks = (int)((threads + 255) / 256);
        k_edge<<<blocks, 256>>>(ei, W2, b2, out, E);
    }
}